// round 4
// baseline (speedup 1.0000x reference)
#include <cuda_runtime.h>

// Shapes (fixed by the problem)
#define N_SAMP 32768
#define D_DIM  256
#define M_ST   4
#define K_CODE 1024

// Output layout (element offsets into f32 d_out)
#define OFF_XQ   0
#define OFF_LOSS 8388608
#define OFF_IDX  8388609
#define OFF_EMB  8519681
#define OFF_AVG  9568257
#define OFF_CS   10616833
#define OUT_TOT  10620929

// Scratch (device globals — no allocation allowed)
__device__ __align__(16) float g_part[256 * 256];   // per-block column partials of x
__device__ int g_flag = 0;                          // producer completion count
__device__ int g_done = 0;                          // consumer completion count

// ---------------------------------------------------------------------------
// Single fused kernel, blockDim = 256, grid = 2956:
//   [0,256)      colsum partials of x (float4) -> g_part, then signal g_flag
//   [256,260)    cluster_size outputs
//   [260,388)    zero-fill loss + indices
//   [388,2436)   x_q_total broadcast writes
//   [2436,2948)  emb/avg outputs for k != 0
//   [2948,2952)  k==0 rows: spin on g_flag, reduce g_part -> Sx, write row0
// ---------------------------------------------------------------------------
__global__ void __launch_bounds__(256) rvq_fused(
        const float* __restrict__ x,
        const float* __restrict__ emb,
        const float* __restrict__ avg,
        const float* __restrict__ cs_in,
        float* __restrict__ out, int out_size) {
    const int b = blockIdx.x;
    const int tid = threadIdx.x;

    if (b < 256) {
        // ---- colsum partial: block b covers rows [b*128, b*128+128).
        const int r_off = tid >> 6;
        const int c4 = tid & 63;
        const float4* x4 = (const float4*)x;
        float4 acc = make_float4(0.f, 0.f, 0.f, 0.f);
        const long base = (long)b * 128 * 64 + c4;
#pragma unroll 8
        for (int r = r_off; r < 128; r += 4) {
            float4 v = x4[base + (long)r * 64];
            acc.x += v.x; acc.y += v.y; acc.z += v.z; acc.w += v.w;
        }
        __shared__ float4 s4[256];
        s4[tid] = acc;
        __syncthreads();
        if (tid < 64) {
            float4 a = s4[tid], b1 = s4[tid + 64], c = s4[tid + 128], d = s4[tid + 192];
            float4 r;
            r.x = ((a.x + b1.x) + c.x) + d.x;
            r.y = ((a.y + b1.y) + c.y) + d.y;
            r.z = ((a.z + b1.z) + c.z) + d.z;
            r.w = ((a.w + b1.w) + c.w) + d.w;
            ((float4*)g_part)[b * 64 + tid] = r;
        }
        __syncthreads();
        if (tid == 0) {
            __threadfence();                 // publish g_part before signaling
            atomicAdd(&g_flag, 1);
        }
    } else if (b < 260) {
        // ---- cluster_size outputs for stage i
        const int i = b - 256;
#pragma unroll
        for (int j = 0; j < 4; ++j) {
            const int k = tid + j * 256;
            const float c = cs_in[i * K_CODE + k] * 0.99f +
                            ((k == 0) ? 327.68f : 0.f);
            const int o = OFF_CS + i * K_CODE + k;
            if (o < out_size) out[o] = c;
        }
    } else if (b < 388) {
        // ---- zero-fill loss + indices: float4 idx [2097152, 2129920) + tail
        const int j = (b - 260) * 256 + tid;             // [0, 32768)
        const long e4 = 2097152L + j;
        if (e4 * 4 + 3 < out_size)
            ((float4*)out)[e4] = make_float4(0.f, 0.f, 0.f, 0.f);
        if (j == 0 && 8519680 < out_size) out[8519680] = 0.f;
    } else if (b < 2436) {
        // ---- x_q_total: each thread stores 4 float4 at stride 524288
        const long u = (long)(b - 388) * 256 + tid;      // [0, 524288)
        const int c4 = (int)(u & 63);
        const float4* e4p = (const float4*)emb;
        float4 s0 = e4p[0 * 65536 + c4];
        float4 s1 = e4p[1 * 65536 + c4];
        float4 s2 = e4p[2 * 65536 + c4];
        float4 s3 = e4p[3 * 65536 + c4];
        float4 s;
        s.x = ((s0.x + s1.x) + s2.x) + s3.x;
        s.y = ((s0.y + s1.y) + s2.y) + s3.y;
        s.z = ((s0.z + s1.z) + s2.z) + s3.z;
        s.w = ((s0.w + s1.w) + s2.w) + s3.w;
#pragma unroll
        for (int j = 0; j < 4; ++j) {
            const long e4 = u + (long)j * 524288;        // < 2097152
            if (e4 * 4 + 3 < out_size) ((float4*)out)[e4] = s;
        }
    } else if (b < 2948) {
        // ---- emb/avg for k != 0. blk in [0,512): 128 blocks/stage, 8 rows each.
        const int blk = b - 2436;
        const int i = blk >> 7;                          // stage
        const int r0 = (blk & 127) * 8;                  // first k of this block
        __shared__ float red[256];
        {
            const float* csr = cs_in + i * K_CODE;
            float s = ((csr[tid] + csr[tid + 256]) + csr[tid + 512]) + csr[tid + 768];
            red[tid] = s;
            __syncthreads();
            for (int st = 128; st > 0; st >>= 1) {
                if (tid < st) red[tid] += red[tid + st];
                __syncthreads();
            }
        }
        const float n = 0.99f * red[0] + 327.68f;
        const float denom = n + 1024.0f * 1e-5f;
#pragma unroll
        for (int r = 0; r < 8; ++r) {
            const int k = r0 + r;
            if (k == 0) continue;                        // handled by tail blocks
            const int row = i * K_CODE + k;
            const float c = cs_in[row] * 0.99f;
            const float w = (c + 1e-5f) / denom * n;
            const float iw = 1.0f / w;
            const int t = row * D_DIM + tid;
            const float na = 0.99f * avg[t];             // sum_term == 0 for k != 0
            const int oa = OFF_AVG + t;
            const int oe = OFF_EMB + t;
            if (oa < out_size) out[oa] = na;
            if (oe < out_size) out[oe] = na * iw;
        }
    } else {
        // ---- k==0 rows for stage i. 4 blocks of 256 threads; d = tid.
        const int i = b - 2948;
        // n_i = 0.99 * sum(cs[i,:]) + 327.68
        __shared__ float red[256];
        {
            const float* csr = cs_in + i * K_CODE;
            float s = ((csr[tid] + csr[tid + 256]) + csr[tid + 512]) + csr[tid + 768];
            red[tid] = s;
            __syncthreads();
            for (int st = 128; st > 0; st >>= 1) {
                if (tid < st) red[tid] += red[tid + st];
                __syncthreads();
            }
        }
        const float n = 0.99f * red[0] + 327.68f;

        // Wait for all 256 colsum producers (scheduled in wave 1; we are last wave)
        if (tid == 0) {
            while (atomicAdd(&g_flag, 0) < 256) { }
        }
        __syncthreads();
        __threadfence();                                 // acquire g_part

        // Sx[d] = fixed-order sum of 256 partials
        const int d = tid;
        float sx = 0.f;
#pragma unroll 8
        for (int p = 0; p < 256; ++p)
            sx += g_part[p * D_DIM + d];

        // P_i[d] = sum_{j<i} emb[j,0,d]
        float pi = 0.f;
        for (int j = 0; j < i; ++j) pi += emb[(size_t)j * K_CODE * D_DIM + d];
        const float sum_term = sx - 32768.0f * pi;
        const int t = i * K_CODE * D_DIM + d;            // (i, 0, d)
        const float na = 0.99f * avg[t] + 0.01f * sum_term;
        const float c0 = cs_in[i * K_CODE] * 0.99f + 327.68f;
        const float w = (c0 + 1e-5f) / (n + 1024.0f * 1e-5f) * n;
        const int oa = OFF_AVG + t;
        const int oe = OFF_EMB + t;
        if (oa < out_size) out[oa] = na;
        if (oe < out_size) out[oe] = na / w;

        // Reset flags for the next graph replay (last consumer does it)
        __syncthreads();
        if (tid == 0) {
            if (atomicAdd(&g_done, 1) == 3) {
                g_done = 0;
                __threadfence();
                atomicExch(&g_flag, 0);
            }
        }
    }
}

extern "C" void kernel_launch(void* const* d_in, const int* in_sizes, int n_in,
                              void* d_out, int out_size) {
    const float* x   = (const float*)d_in[0];  // [N, D]
    const float* emb = (const float*)d_in[1];  // [M, K, D]
    const float* avg = (const float*)d_in[2];  // [M, K, D]
    const float* cs  = (const float*)d_in[3];  // [M, K]
    float* out = (float*)d_out;

    rvq_fused<<<2952, 256>>>(x, emb, avg, cs, out, out_size);
}

// round 5
// speedup vs baseline: 1.2264x; 1.2264x over previous
#include <cuda_runtime.h>

// Shapes (fixed by the problem)
#define N_SAMP 32768
#define D_DIM  256
#define M_ST   4
#define K_CODE 1024

// Output layout (element offsets into f32 d_out)
#define OFF_XQ   0
#define OFF_LOSS 8388608
#define OFF_IDX  8388609
#define OFF_EMB  8519681
#define OFF_AVG  9568257
#define OFF_CS   10616833
#define OUT_TOT  10620929

// Scratch (device global — no allocation allowed)
__device__ __align__(16) float g_part[256 * 256];   // per-block column partials of x

// ---------------------------------------------------------------------------
// K0: colsum partials of x. 256 blocks x 256 threads, float4 loads.
// Block b sums rows [b*128, b*128+128) -> g_part[b][0..255].
// ---------------------------------------------------------------------------
__global__ void __launch_bounds__(256) k0_colsum(const float* __restrict__ x) {
    const int b = blockIdx.x;
    const int tid = threadIdx.x;
    const int r_off = tid >> 6;          // row phase 0..3
    const int c4 = tid & 63;             // float4 column
    const float4* x4 = (const float4*)x;
    float4 acc = make_float4(0.f, 0.f, 0.f, 0.f);
    const long base = (long)b * 128 * 64 + c4;
#pragma unroll 8
    for (int r = r_off; r < 128; r += 4) {
        float4 v = x4[base + (long)r * 64];
        acc.x += v.x; acc.y += v.y; acc.z += v.z; acc.w += v.w;
    }
    __shared__ float4 s4[256];
    s4[tid] = acc;
    __syncthreads();
    if (tid < 64) {
        float4 a = s4[tid], b1 = s4[tid + 64], c = s4[tid + 128], d = s4[tid + 192];
        float4 r;
        r.x = ((a.x + b1.x) + c.x) + d.x;
        r.y = ((a.y + b1.y) + c.y) + d.y;
        r.z = ((a.z + b1.z) + c.z) + d.z;
        r.w = ((a.w + b1.w) + c.w) + d.w;
        ((float4*)g_part)[b * 64 + tid] = r;
    }
}

// ---------------------------------------------------------------------------
// K1: everything else. blockDim = 256, grid = 2696. Low bids = latency-heavy
// work so it starts in wave 1 and hides under the streaming bulk:
//   [0,4)        k==0 rows (reads g_part — ordered by kernel boundary)
//   [4,8)        cluster_size outputs
//   [8,136)      zero-fill loss + indices
//   [136,648)    emb/avg outputs for k != 0
//   [648,2696)   x_q_total broadcast writes (bulk)
// ---------------------------------------------------------------------------
__global__ void __launch_bounds__(256) k1_rest(
        const float* __restrict__ emb,
        const float* __restrict__ avg,
        const float* __restrict__ cs_in,
        float* __restrict__ out, int out_size) {
    const int b = blockIdx.x;
    const int tid = threadIdx.x;

    if (b < 4) {
        // ---- k==0 row of stage i. d = tid.
        const int i = b;
        // n_i = 0.99 * sum(cs[i,:]) + 327.68  (fixed-order tree)
        __shared__ float red[256];
        {
            const float* csr = cs_in + i * K_CODE;
            float s = ((csr[tid] + csr[tid + 256]) + csr[tid + 512]) + csr[tid + 768];
            red[tid] = s;
            __syncthreads();
            for (int st = 128; st > 0; st >>= 1) {
                if (tid < st) red[tid] += red[tid + st];
                __syncthreads();
            }
        }
        const float n = 0.99f * red[0] + 327.68f;

        // Sx[d] = fixed-order sum of 256 partials (L2-hot, high MLP)
        const int d = tid;
        float sx = 0.f;
#pragma unroll 16
        for (int p = 0; p < 256; ++p)
            sx += g_part[p * D_DIM + d];

        // P_i[d] = sum_{j<i} emb[j,0,d]
        float pi = 0.f;
        for (int j = 0; j < i; ++j) pi += emb[(size_t)j * K_CODE * D_DIM + d];
        const float sum_term = sx - 32768.0f * pi;
        const int t = i * K_CODE * D_DIM + d;            // (i, 0, d)
        const float na = 0.99f * avg[t] + 0.01f * sum_term;
        const float c0 = cs_in[i * K_CODE] * 0.99f + 327.68f;
        const float w = (c0 + 1e-5f) / (n + 1024.0f * 1e-5f) * n;
        const int oa = OFF_AVG + t;
        const int oe = OFF_EMB + t;
        if (oa < out_size) out[oa] = na;
        if (oe < out_size) out[oe] = na / w;
    } else if (b < 8) {
        // ---- cluster_size outputs for stage i
        const int i = b - 4;
#pragma unroll
        for (int j = 0; j < 4; ++j) {
            const int k = tid + j * 256;
            const float c = cs_in[i * K_CODE + k] * 0.99f +
                            ((k == 0) ? 327.68f : 0.f);
            const int o = OFF_CS + i * K_CODE + k;
            if (o < out_size) out[o] = c;
        }
    } else if (b < 136) {
        // ---- zero-fill loss + indices: float4 idx [2097152, 2129920) + tail
        const int j = (b - 8) * 256 + tid;               // [0, 32768)
        const long e4 = 2097152L + j;
        if (e4 * 4 + 3 < out_size)
            ((float4*)out)[e4] = make_float4(0.f, 0.f, 0.f, 0.f);
        if (j == 0 && 8519680 < out_size) out[8519680] = 0.f;
    } else if (b < 648) {
        // ---- emb/avg for k != 0. blk in [0,512): 128 blocks/stage, 8 rows each.
        const int blk = b - 136;
        const int i = blk >> 7;                          // stage
        const int r0 = (blk & 127) * 8;                  // first k of this block
        __shared__ float red[256];
        {
            const float* csr = cs_in + i * K_CODE;
            float s = ((csr[tid] + csr[tid + 256]) + csr[tid + 512]) + csr[tid + 768];
            red[tid] = s;
            __syncthreads();
            for (int st = 128; st > 0; st >>= 1) {
                if (tid < st) red[tid] += red[tid + st];
                __syncthreads();
            }
        }
        const float n = 0.99f * red[0] + 327.68f;
        const float denom = n + 1024.0f * 1e-5f;
#pragma unroll
        for (int r = 0; r < 8; ++r) {
            const int k = r0 + r;
            if (k == 0) continue;                        // handled by b < 4
            const int row = i * K_CODE + k;
            const float c = cs_in[row] * 0.99f;
            const float w = (c + 1e-5f) / denom * n;
            const float iw = 1.0f / w;
            const int t = row * D_DIM + tid;
            const float na = 0.99f * avg[t];             // sum_term == 0 for k != 0
            const int oa = OFF_AVG + t;
            const int oe = OFF_EMB + t;
            if (oa < out_size) out[oa] = na;
            if (oe < out_size) out[oe] = na * iw;
        }
    } else {
        // ---- x_q_total: each thread stores 4 float4 at stride 524288
        const long u = (long)(b - 648) * 256 + tid;      // [0, 524288)
        const int c4 = (int)(u & 63);
        const float4* e4p = (const float4*)emb;
        float4 s0 = e4p[0 * 65536 + c4];
        float4 s1 = e4p[1 * 65536 + c4];
        float4 s2 = e4p[2 * 65536 + c4];
        float4 s3 = e4p[3 * 65536 + c4];
        float4 s;
        s.x = ((s0.x + s1.x) + s2.x) + s3.x;
        s.y = ((s0.y + s1.y) + s2.y) + s3.y;
        s.z = ((s0.z + s1.z) + s2.z) + s3.z;
        s.w = ((s0.w + s1.w) + s2.w) + s3.w;
#pragma unroll
        for (int j = 0; j < 4; ++j) {
            const long e4 = u + (long)j * 524288;        // < 2097152
            if (e4 * 4 + 3 < out_size) ((float4*)out)[e4] = s;
        }
    }
}

extern "C" void kernel_launch(void* const* d_in, const int* in_sizes, int n_in,
                              void* d_out, int out_size) {
    const float* x   = (const float*)d_in[0];  // [N, D]
    const float* emb = (const float*)d_in[1];  // [M, K, D]
    const float* avg = (const float*)d_in[2];  // [M, K, D]
    const float* cs  = (const float*)d_in[3];  // [M, K]
    float* out = (float*)d_out;

    k0_colsum<<<256, 256>>>(x);
    k1_rest<<<2696, 256>>>(emb, avg, cs, out, out_size);
}

// round 6
// speedup vs baseline: 1.3384x; 1.0914x over previous
#include <cuda_runtime.h>

// Shapes (fixed by the problem)
#define N_SAMP 32768
#define D_DIM  256
#define M_ST   4
#define K_CODE 1024

// Output layout (element offsets into f32 d_out)
#define OFF_XQ   0
#define OFF_LOSS 8388608
#define OFF_IDX  8388609
#define OFF_EMB  8519681
#define OFF_AVG  9568257
#define OFF_CS   10616833
#define OUT_TOT  10620929

// Scratch (device global — no allocation allowed)
__device__ __align__(16) float g_part[256 * 256];   // per-block column partials of x

// ---------------------------------------------------------------------------
// K0: colsum partials of x. 256 blocks x 256 threads, float4 loads.
// Block b sums rows [b*128, b*128+128) -> g_part[b][0..255]. ~8.6TB/s already.
// ---------------------------------------------------------------------------
__global__ void __launch_bounds__(256) k0_colsum(const float* __restrict__ x) {
    const int b = blockIdx.x;
    const int tid = threadIdx.x;
    const int r_off = tid >> 6;          // row phase 0..3
    const int c4 = tid & 63;             // float4 column
    const float4* x4 = (const float4*)x;
    float4 acc = make_float4(0.f, 0.f, 0.f, 0.f);
    const long base = (long)b * 128 * 64 + c4;
#pragma unroll 8
    for (int r = r_off; r < 128; r += 4) {
        float4 v = x4[base + (long)r * 64];
        acc.x += v.x; acc.y += v.y; acc.z += v.z; acc.w += v.w;
    }
    __shared__ float4 s4[256];
    s4[tid] = acc;
    __syncthreads();
    if (tid < 64) {
        float4 a = s4[tid], b1 = s4[tid + 64], c = s4[tid + 128], d = s4[tid + 192];
        float4 r;
        r.x = ((a.x + b1.x) + c.x) + d.x;
        r.y = ((a.y + b1.y) + c.y) + d.y;
        r.z = ((a.z + b1.z) + c.z) + d.z;
        r.w = ((a.w + b1.w) + c.w) + d.w;
        ((float4*)g_part)[b * 64 + tid] = r;
    }
}

// ---------------------------------------------------------------------------
// K1: everything else. blockDim = 256, grid = 1064 (~one wave):
//   [0,4)        k==0 rows (reads g_part — ordered by kernel boundary)
//   [4,8)        cluster_size outputs
//   [8,520)      emb/avg outputs for k != 0
//   [520,1032)   x_q_total: 16 coalesced STG.128 per thread, s computed once
//   [1032,1064)  zero-fill loss + indices (4 stores/thread)
// ---------------------------------------------------------------------------
__global__ void __launch_bounds__(256) k1_rest(
        const float* __restrict__ emb,
        const float* __restrict__ avg,
        const float* __restrict__ cs_in,
        float* __restrict__ out, int out_size) {
    const int b = blockIdx.x;
    const int tid = threadIdx.x;

    if (b < 4) {
        // ---- k==0 row of stage i. d = tid.
        const int i = b;
        __shared__ float red[256];
        {
            const float* csr = cs_in + i * K_CODE;
            float s = ((csr[tid] + csr[tid + 256]) + csr[tid + 512]) + csr[tid + 768];
            red[tid] = s;
            __syncthreads();
            for (int st = 128; st > 0; st >>= 1) {
                if (tid < st) red[tid] += red[tid + st];
                __syncthreads();
            }
        }
        const float n = 0.99f * red[0] + 327.68f;

        // Sx[d] = fixed-order sum of 256 partials (L2-hot, high MLP)
        const int d = tid;
        float sx = 0.f;
#pragma unroll 16
        for (int p = 0; p < 256; ++p)
            sx += g_part[p * D_DIM + d];

        float pi = 0.f;
        for (int j = 0; j < i; ++j) pi += emb[(size_t)j * K_CODE * D_DIM + d];
        const float sum_term = sx - 32768.0f * pi;
        const int t = i * K_CODE * D_DIM + d;            // (i, 0, d)
        const float na = 0.99f * avg[t] + 0.01f * sum_term;
        const float c0 = cs_in[i * K_CODE] * 0.99f + 327.68f;
        const float w = (c0 + 1e-5f) / (n + 1024.0f * 1e-5f) * n;
        const int oa = OFF_AVG + t;
        const int oe = OFF_EMB + t;
        if (oa < out_size) out[oa] = na;
        if (oe < out_size) out[oe] = na / w;
    } else if (b < 8) {
        // ---- cluster_size outputs for stage i
        const int i = b - 4;
#pragma unroll
        for (int j = 0; j < 4; ++j) {
            const int k = tid + j * 256;
            const float c = cs_in[i * K_CODE + k] * 0.99f +
                            ((k == 0) ? 327.68f : 0.f);
            const int o = OFF_CS + i * K_CODE + k;
            if (o < out_size) out[o] = c;
        }
    } else if (b < 520) {
        // ---- emb/avg for k != 0. blk in [0,512): 128 blocks/stage, 8 rows each.
        const int blk = b - 8;
        const int i = blk >> 7;                          // stage
        const int r0 = (blk & 127) * 8;                  // first k of this block
        __shared__ float red[256];
        {
            const float* csr = cs_in + i * K_CODE;
            float s = ((csr[tid] + csr[tid + 256]) + csr[tid + 512]) + csr[tid + 768];
            red[tid] = s;
            __syncthreads();
            for (int st = 128; st > 0; st >>= 1) {
                if (tid < st) red[tid] += red[tid + st];
                __syncthreads();
            }
        }
        const float n = 0.99f * red[0] + 327.68f;
        const float denom = n + 1024.0f * 1e-5f;
#pragma unroll
        for (int r = 0; r < 8; ++r) {
            const int k = r0 + r;
            if (k == 0) continue;                        // handled by b < 4
            const int row = i * K_CODE + k;
            const float c = cs_in[row] * 0.99f;
            const float w = (c + 1e-5f) / denom * n;
            const float iw = 1.0f / w;
            const int t = row * D_DIM + tid;
            const float na = 0.99f * avg[t];             // sum_term == 0 for k != 0
            const int oa = OFF_AVG + t;
            const int oe = OFF_EMB + t;
            if (oa < out_size) out[oa] = na;
            if (oe < out_size) out[oe] = na * iw;
        }
    } else if (b < 1032) {
        // ---- x_q_total: compute s once, then 16 coalesced STG.128.
        const int v = (b - 520) * 256 + tid;             // [0, 131072)
        const int c4 = v & 63;                           // float4 column (const per thread)
        const float4* e4p = (const float4*)emb;
        float4 s0 = e4p[0 * 65536 + c4];
        float4 s1 = e4p[1 * 65536 + c4];
        float4 s2 = e4p[2 * 65536 + c4];
        float4 s3 = e4p[3 * 65536 + c4];
        float4 s;
        s.x = ((s0.x + s1.x) + s2.x) + s3.x;
        s.y = ((s0.y + s1.y) + s2.y) + s3.y;
        s.z = ((s0.z + s1.z) + s2.z) + s3.z;
        s.w = ((s0.w + s1.w) + s2.w) + s3.w;
        float4* o4 = (float4*)out;
#pragma unroll
        for (int j = 0; j < 16; ++j) {
            const long e4 = (long)v + (long)j * 131072;  // < 2097152
            if (e4 * 4 + 3 < out_size) o4[e4] = s;
        }
    } else {
        // ---- zero-fill loss + indices: float4 idx [2097152, 2129920) + tail
        const int v = (b - 1032) * 256 + tid;            // [0, 8192)
        const float4 z = make_float4(0.f, 0.f, 0.f, 0.f);
#pragma unroll
        for (int j = 0; j < 4; ++j) {
            const long e4 = 2097152L + v + (long)j * 8192;
            if (e4 * 4 + 3 < out_size) ((float4*)out)[e4] = z;
        }
        if (v == 0 && 8519680 < out_size) out[8519680] = 0.f;
    }
}

extern "C" void kernel_launch(void* const* d_in, const int* in_sizes, int n_in,
                              void* d_out, int out_size) {
    const float* x   = (const float*)d_in[0];  // [N, D]
    const float* emb = (const float*)d_in[1];  // [M, K, D]
    const float* avg = (const float*)d_in[2];  // [M, K, D]
    const float* cs  = (const float*)d_in[3];  // [M, K]
    float* out = (float*)d_out;

    k0_colsum<<<256, 256>>>(x);
    k1_rest<<<1064, 256>>>(emb, avg, cs, out, out_size);
}